// round 1
// baseline (speedup 1.0000x reference)
#include <cuda_runtime.h>

#define NB 512
#define NL 64
#define ND 784
#define NE 128
#define NI 32
#define NC 10
#define MT (NB*NL)      // 32768 rows
#define NTOT 160        // NE + NI

// Scratch for the input projection u = [x@Wxe_p^T | x@Wxi_p^T], [MT, 160]
__device__ float g_u[(long long)MT * NTOT];

// ---------------------------------------------------------------------------
// Kernel 1: C[m][n] = sum_k X[m][k] * relu(W[n][k]),  W = concat(Wxe, Wxi)
// CTA tile: 64 (M) x 160 (N), K-tile 16. 256 threads, 4x10 per-thread tile.
// ---------------------------------------------------------------------------
__global__ __launch_bounds__(256) void proj_kernel(
    const float* __restrict__ X,
    const float* __restrict__ Wxe,
    const float* __restrict__ Wxi)
{
    __shared__ __align__(16) float Xs[16][68];    // k-major, padded
    __shared__ __align__(16) float Ws[16][164];   // k-major, padded

    const int t  = threadIdx.x;
    const int m0 = blockIdx.x * 64;
    const int tm = t & 15;      // m-group (4 rows)
    const int tn = t >> 4;      // n-group (10 cols)

    float acc[4][10];
#pragma unroll
    for (int r = 0; r < 4; r++)
#pragma unroll
        for (int j = 0; j < 10; j++) acc[r][j] = 0.f;

    const int lm = t >> 2;            // 0..63 (X loader row)
    const int lq = (t & 3) << 2;      // 0,4,8,12 (X loader k quad)
    const int wi0 = t, wi1 = t + 256, wi2 = t + 512;   // W loader (640 float4s)

    for (int k0 = 0; k0 < ND; k0 += 16) {
        // stage loads in registers
        float4 xv = *reinterpret_cast<const float4*>(X + (long long)(m0 + lm) * ND + k0 + lq);
        float4 wv0, wv1, wv2;
        {
            int n = wi0 >> 2, q = (wi0 & 3) << 2;
            const float* wr = (n < NE) ? (Wxe + (long long)n * ND) : (Wxi + (long long)(n - NE) * ND);
            wv0 = *reinterpret_cast<const float4*>(wr + k0 + q);
        }
        {
            int n = wi1 >> 2, q = (wi1 & 3) << 2;
            const float* wr = (n < NE) ? (Wxe + (long long)n * ND) : (Wxi + (long long)(n - NE) * ND);
            wv1 = *reinterpret_cast<const float4*>(wr + k0 + q);
        }
        if (wi2 < 640) {
            int n = wi2 >> 2, q = (wi2 & 3) << 2;
            const float* wr = (n < NE) ? (Wxe + (long long)n * ND) : (Wxi + (long long)(n - NE) * ND);
            wv2 = *reinterpret_cast<const float4*>(wr + k0 + q);
        }
        __syncthreads();   // previous tile's compute done
        Xs[lq + 0][lm] = xv.x; Xs[lq + 1][lm] = xv.y;
        Xs[lq + 2][lm] = xv.z; Xs[lq + 3][lm] = xv.w;
        {
            int n = wi0 >> 2, q = (wi0 & 3) << 2;
            Ws[q + 0][n] = fmaxf(wv0.x, 0.f); Ws[q + 1][n] = fmaxf(wv0.y, 0.f);
            Ws[q + 2][n] = fmaxf(wv0.z, 0.f); Ws[q + 3][n] = fmaxf(wv0.w, 0.f);
        }
        {
            int n = wi1 >> 2, q = (wi1 & 3) << 2;
            Ws[q + 0][n] = fmaxf(wv1.x, 0.f); Ws[q + 1][n] = fmaxf(wv1.y, 0.f);
            Ws[q + 2][n] = fmaxf(wv1.z, 0.f); Ws[q + 3][n] = fmaxf(wv1.w, 0.f);
        }
        if (wi2 < 640) {
            int n = wi2 >> 2, q = (wi2 & 3) << 2;
            Ws[q + 0][n] = fmaxf(wv2.x, 0.f); Ws[q + 1][n] = fmaxf(wv2.y, 0.f);
            Ws[q + 2][n] = fmaxf(wv2.z, 0.f); Ws[q + 3][n] = fmaxf(wv2.w, 0.f);
        }
        __syncthreads();

#pragma unroll
        for (int k = 0; k < 16; k++) {
            float4 a = *reinterpret_cast<const float4*>(&Xs[k][tm << 2]);
            float bv[10];
#pragma unroll
            for (int j = 0; j < 10; j++) bv[j] = Ws[k][tn * 10 + j];
#pragma unroll
            for (int j = 0; j < 10; j++) {
                acc[0][j] = fmaf(a.x, bv[j], acc[0][j]);
                acc[1][j] = fmaf(a.y, bv[j], acc[1][j]);
                acc[2][j] = fmaf(a.z, bv[j], acc[2][j]);
                acc[3][j] = fmaf(a.w, bv[j], acc[3][j]);
            }
        }
    }

#pragma unroll
    for (int r = 0; r < 4; r++) {
        long long m = m0 + (tm << 2) + r;
#pragma unroll
        for (int j = 0; j < 10; j++)
            g_u[m * NTOT + tn * 10 + j] = acc[r][j];
    }
}

// ---------------------------------------------------------------------------
// Kernel 2: EI recurrence. 128 CTAs x 256 threads; each CTA owns 4 batch rows
// through all 64 steps. All relu'd weights resident in smem (padded strides).
// Threads 0..127: exc neuron n=t, all 4 rows (states in regs).
// Threads 128..255: inh neuron j=(t-128)&31, row (t-128)>>5.
// Threads 0..39 additionally compute the 10-class readout each step.
// ---------------------------------------------------------------------------
#define SEP 132   // padded stride for 128-wide rows (float4-friendly, odd quad)
#define SIP 36    // padded stride for 32-wide rows

__global__ __launch_bounds__(256) void rec_kernel(
    const float* __restrict__ Wee, const float* __restrict__ Wie,
    const float* __restrict__ Wei, const float* __restrict__ Wii,
    const float* __restrict__ be,  const float* __restrict__ bi,
    const float* __restrict__ Wro, const float* __restrict__ bro,
    float* __restrict__ out)
{
    extern __shared__ __align__(16) float sm[];
    float* Wee_s = sm;                       // [128][SEP]
    float* Wie_s = Wee_s + 128 * SEP;        // [128][SIP]
    float* Wei_s = Wie_s + 128 * SIP;        // [32][SEP]
    float* Wii_s = Wei_s + 32 * SEP;         // [32][SIP]
    float* Wro_s = Wii_s + 32 * SIP;         // [10][SEP]
    float* sE    = Wro_s + 10 * SEP;         // [4][SEP]  r_e per row
    float* sI    = sE + 4 * SEP;             // [4][SIP]  r_i per row

    const int t  = threadIdx.x;
    const int b0 = blockIdx.x * 4;

    // cooperative weight staging (relu applied here; Wro unrectified)
    for (int i = t; i < 128 * 128; i += 256) { int n = i >> 7, k = i & 127; Wee_s[n * SEP + k] = fmaxf(Wee[i], 0.f); }
    for (int i = t; i < 128 * 32;  i += 256) { int n = i >> 5, j = i & 31;  Wie_s[n * SIP + j] = fmaxf(Wie[i], 0.f); }
    for (int i = t; i < 32 * 128;  i += 256) { int j = i >> 7, k = i & 127; Wei_s[j * SEP + k] = fmaxf(Wei[i], 0.f); }
    for (int i = t; i < 32 * 32;   i += 256) { int j = i >> 5, m = i & 31;  Wii_s[j * SIP + m] = fmaxf(Wii[i], 0.f); }
    for (int i = t; i < 10 * 128;  i += 256) { int c = i >> 7, n = i & 127; Wro_s[c * SEP + n] = Wro[i]; }
    for (int i = t; i < 4 * SEP;   i += 256) sE[i] = 0.f;
    for (int i = t; i < 4 * SIP;   i += 256) sI[i] = 0.f;
    __syncthreads();

    const bool isE = (t < 128);
    const int ti = t - 128;
    const int jj = ti & 31;
    const int ir = ti >> 5;

    float e_st[4] = {0.f, 0.f, 0.f, 0.f};
    float i_st = 0.f;
    const float be_n  = isE ? be[t] : 0.f;
    const float bi_j  = (!isE) ? bi[jj] : 0.f;
    const float bro_c = (t < 40) ? bro[t % 10] : 0.f;

    // flat output layout (return-tuple order, flattened)
    float* out_logits = out;
    float* out_last   = out_logits + (long long)NB * NL * NC;
    float* out_re     = out_last   + (long long)NB * NC;
    float* out_ri     = out_re     + (long long)NB * NL * NE;
    float* out_bale   = out_ri     + (long long)NB * NL * NI;
    float* out_bali   = out_bale   + (long long)NB * NL * NE;

    for (int st = 0; st < NL; st++) {
        float acc[4], inh[4];
        float iacc = 0.f, iinh = 0.f;

        // ---- phase A: accumulate balances from OLD r_e / r_i ----
        if (isE) {
            const float* up = g_u + ((long long)b0 * NL + st) * NTOT + t;
#pragma unroll
            for (int r = 0; r < 4; r++) {
                acc[r] = up[(long long)r * NL * NTOT];
                inh[r] = 0.f;
            }
            const float4* wp = reinterpret_cast<const float4*>(Wee_s + t * SEP);
#pragma unroll 8
            for (int k4 = 0; k4 < 32; k4++) {
                float4 w = wp[k4];
#pragma unroll
                for (int r = 0; r < 4; r++) {
                    float4 a = *reinterpret_cast<const float4*>(sE + r * SEP + (k4 << 2));
                    acc[r] = fmaf(w.x, a.x, acc[r]);
                    acc[r] = fmaf(w.y, a.y, acc[r]);
                    acc[r] = fmaf(w.z, a.z, acc[r]);
                    acc[r] = fmaf(w.w, a.w, acc[r]);
                }
            }
            const float4* wq = reinterpret_cast<const float4*>(Wie_s + t * SIP);
#pragma unroll
            for (int j4 = 0; j4 < 8; j4++) {
                float4 w = wq[j4];
#pragma unroll
                for (int r = 0; r < 4; r++) {
                    float4 s = *reinterpret_cast<const float4*>(sI + r * SIP + (j4 << 2));
                    inh[r] = fmaf(w.x, s.x, inh[r]);
                    inh[r] = fmaf(w.y, s.y, inh[r]);
                    inh[r] = fmaf(w.z, s.z, inh[r]);
                    inh[r] = fmaf(w.w, s.w, inh[r]);
                }
            }
        } else {
            iacc = g_u[((long long)(b0 + ir) * NL + st) * NTOT + NE + jj];
            const float4* wp = reinterpret_cast<const float4*>(Wei_s + jj * SEP);
#pragma unroll 8
            for (int k4 = 0; k4 < 32; k4++) {
                float4 w = wp[k4];
                float4 a = *reinterpret_cast<const float4*>(sE + ir * SEP + (k4 << 2));
                iacc = fmaf(w.x, a.x, iacc);
                iacc = fmaf(w.y, a.y, iacc);
                iacc = fmaf(w.z, a.z, iacc);
                iacc = fmaf(w.w, a.w, iacc);
            }
            const float4* wq = reinterpret_cast<const float4*>(Wii_s + jj * SIP);
#pragma unroll
            for (int m4 = 0; m4 < 8; m4++) {
                float4 w = wq[m4];
                float4 s = *reinterpret_cast<const float4*>(sI + ir * SIP + (m4 << 2));
                iinh = fmaf(w.x, s.x, iinh);
                iinh = fmaf(w.y, s.y, iinh);
                iinh = fmaf(w.z, s.z, iinh);
                iinh = fmaf(w.w, s.w, iinh);
            }
        }
        __syncthreads();   // all reads of old sE/sI complete

        // ---- phase B: state update, publish new r_e/r_i, write outputs ----
        if (isE) {
#pragma unroll
            for (int r = 0; r < 4; r++) {
                float bal = acc[r] - inh[r];
                long long row = (long long)(b0 + r) * NL + st;
                out_bale[row * NE + t] = bal;
                e_st[r] = 0.5f * e_st[r] + 0.5f * (bal + be_n);
                float rv = fmaxf(e_st[r], 0.f);
                out_re[row * NE + t] = rv;
                sE[r * SEP + t] = rv;
            }
        } else {
            float bal = iacc - iinh;
            long long row = (long long)(b0 + ir) * NL + st;
            out_bali[row * NI + jj] = bal;
            i_st = 0.5f * i_st + 0.5f * (bal + bi_j);
            float rv = fmaxf(i_st, 0.f);
            out_ri[row * NI + jj] = rv;
            sI[ir * SIP + jj] = rv;
        }
        __syncthreads();   // new sE visible for readout + next step

        // ---- phase C: readout from NEW r_e (overlaps next phase A) ----
        if (t < 40) {
            int c = t % 10, rr = t / 10;
            float lacc = bro_c;
            const float4* wr = reinterpret_cast<const float4*>(Wro_s + c * SEP);
#pragma unroll 8
            for (int n4 = 0; n4 < 32; n4++) {
                float4 w = wr[n4];
                float4 a = *reinterpret_cast<const float4*>(sE + rr * SEP + (n4 << 2));
                lacc = fmaf(w.x, a.x, lacc);
                lacc = fmaf(w.y, a.y, lacc);
                lacc = fmaf(w.z, a.z, lacc);
                lacc = fmaf(w.w, a.w, lacc);
            }
            long long row = (long long)(b0 + rr) * NL + st;
            out_logits[row * NC + c] = lacc;
            if (st == NL - 1) out_last[(long long)(b0 + rr) * NC + c] = lacc;
        }
    }
}

// ---------------------------------------------------------------------------
extern "C" void kernel_launch(void* const* d_in, const int* in_sizes, int n_in,
                              void* d_out, int out_size) {
    const float* x   = (const float*)d_in[0];
    const float* Wxe = (const float*)d_in[1];
    const float* Wxi = (const float*)d_in[2];
    const float* Wee = (const float*)d_in[3];
    const float* Wie = (const float*)d_in[4];
    const float* Wei = (const float*)d_in[5];
    const float* Wii = (const float*)d_in[6];
    const float* be  = (const float*)d_in[7];
    const float* bi  = (const float*)d_in[8];
    const float* Wro = (const float*)d_in[9];
    const float* bro = (const float*)d_in[10];
    float* out = (float*)d_out;

    proj_kernel<<<MT / 64, 256>>>(x, Wxe, Wxi);

    const int smem_bytes = (128 * SEP + 128 * SIP + 32 * SEP + 32 * SIP +
                            10 * SEP + 4 * SEP + 4 * SIP) * (int)sizeof(float);
    cudaFuncSetAttribute(rec_kernel, cudaFuncAttributeMaxDynamicSharedMemorySize, smem_bytes);
    rec_kernel<<<NB / 4, 256, smem_bytes>>>(Wee, Wie, Wei, Wii, be, bi, Wro, bro, out);
}

// round 3
// speedup vs baseline: 1.7543x; 1.7543x over previous
#include <cuda_runtime.h>
#include <cuda_bf16.h>
#include <cstdint>

#define NB 512
#define NL 64
#define ND 784
#define NE 128
#define NI 32
#define NC 10
#define MT (NB*NL)      // 32768 rows
#define NTOT 160
#define NKS 49          // K steps of 16 (784 = 49*16)
#define NNT 20          // N tiles of 8 (160 = 20*8)

// Projection scratch u = [x@relu(Wxe)^T | x@relu(Wxi)^T], [MT, 160] fp32
__device__ float g_u[(long long)MT * NTOT];
// W in mma-fragment layout: [ks(49)][nt(20)][lane(32)] u64 = (b0b1, b2b3)
__device__ unsigned long long g_Whi[NKS * NNT * 32];
__device__ unsigned long long g_Wlo[NKS * NNT * 32];

// ---------------------------------------------------------------------------
// bf16 split helpers (round-to-nearest hi, exact residual, rn lo)
// ---------------------------------------------------------------------------
__device__ __forceinline__ uint32_t pack_hi(float a, float b, float& ra, float& rb) {
    __nv_bfloat16 ha = __float2bfloat16(a), hb = __float2bfloat16(b);
    ra = a - __bfloat162float(ha);
    rb = b - __bfloat162float(hb);
    return (uint32_t)__bfloat16_as_ushort(ha) | ((uint32_t)__bfloat16_as_ushort(hb) << 16);
}
__device__ __forceinline__ uint32_t pack_bf(float a, float b) {
    return (uint32_t)__bfloat16_as_ushort(__float2bfloat16(a)) |
           ((uint32_t)__bfloat16_as_ushort(__float2bfloat16(b)) << 16);
}

#define MMA_BF16(d, a, b0_, b1_) \
    asm volatile("mma.sync.aligned.m16n8k16.row.col.f32.bf16.bf16.f32 " \
        "{%0,%1,%2,%3},{%4,%5,%6,%7},{%8,%9},{%0,%1,%2,%3};" \
        : "+f"((d)[0]), "+f"((d)[1]), "+f"((d)[2]), "+f"((d)[3]) \
        : "r"((a).x), "r"((a).y), "r"((a).z), "r"((a).w), "r"(b0_), "r"(b1_))

// ---------------------------------------------------------------------------
// Kernel 0: convert relu(W) -> bf16 hi/lo in B-fragment layout.
// lane l: g=l>>2 (n within ntile), tg=l&3; values (k=2tg,2tg+1,2tg+8,2tg+9).
// ---------------------------------------------------------------------------
__global__ void wconv_kernel(const float* __restrict__ Wxe,
                             const float* __restrict__ Wxi)
{
    int id = blockIdx.x * 256 + threadIdx.x;
    if (id >= NKS * NNT * 32) return;
    int ks = id / (NNT * 32);
    int rem = id % (NNT * 32);
    int nt = rem >> 5, lane = rem & 31;
    int g = lane >> 2, tg = lane & 3;
    int n = nt * 8 + g;
    int k = ks * 16 + tg * 2;
    const float* row = (n < NE) ? (Wxe + (long long)n * ND)
                                : (Wxi + (long long)(n - NE) * ND);
    float v0 = fmaxf(row[k],     0.f), v1 = fmaxf(row[k + 1], 0.f);
    float v8 = fmaxf(row[k + 8], 0.f), v9 = fmaxf(row[k + 9], 0.f);
    float r0, r1, r8, r9;
    uint32_t h01 = pack_hi(v0, v1, r0, r1);
    uint32_t h89 = pack_hi(v8, v9, r8, r9);
    uint32_t l01 = pack_bf(r0, r1);
    uint32_t l89 = pack_bf(r8, r9);
    g_Whi[id] = (unsigned long long)h01 | ((unsigned long long)h89 << 32);
    g_Wlo[id] = (unsigned long long)l01 | ((unsigned long long)l89 << 32);
}

// ---------------------------------------------------------------------------
// Kernel 1: projection via mma.sync bf16x3.  256 CTAs x 256 thr (8 warps).
// CTA: M=128 (warp = 1 mtile of 16 rows), N=160 (20 ntiles), K chunks of 32.
// Double-buffered smem; A packed to fragment layout at store time.
// ---------------------------------------------------------------------------
#define A_HI 0
#define A_LO 8192
#define B_HI 16384
#define B_LO 26624
#define BUFSZ 36864
#define PROJ_SMEM (2*BUFSZ)      // 73728

__global__ __launch_bounds__(256, 2) void proj_kernel(const float* __restrict__ X)
{
    extern __shared__ __align__(16) char sm[];
    const int t = threadIdx.x, wid = t >> 5, lane = t & 31;
    const int g = lane >> 2, tg = lane & 3;
    const int m0 = blockIdx.x * 128;

    // staging role (A): row = t>>1 (0..127), kstep-within-chunk = t&1
    const int srow = t >> 1;
    const int sks  = t & 1;
    const int smt = srow >> 4, sg = srow & 7, srh = (srow >> 3) & 1;
    const int aBase = (((sks * 8 + smt) * 32 + sg * 4) * 16) + srh * 4;

    float acc[20][4];
#pragma unroll
    for (int nt = 0; nt < 20; nt++)
#pragma unroll
        for (int j = 0; j < 4; j++) acc[nt][j] = 0.f;

    auto stage = [&](int buf, int c) {
        const int ksn = (c == 24) ? 1 : 2;
        if (sks < ksn) {
            const float* xr = X + (long long)(m0 + srow) * ND + c * 32 + sks * 16;
            float v[16];
#pragma unroll
            for (int i = 0; i < 4; i++) {
                float4 f = *reinterpret_cast<const float4*>(xr + i * 4);
                v[i*4+0] = f.x; v[i*4+1] = f.y; v[i*4+2] = f.z; v[i*4+3] = f.w;
            }
            char* ah = sm + buf * BUFSZ + A_HI + aBase;
            char* al = sm + buf * BUFSZ + A_LO + aBase;
#pragma unroll
            for (int i = 0; i < 4; i++)
#pragma unroll
                for (int p = 0; p < 2; p++) {
                    int e = i * 4 + p * 2;
                    float lo0, lo1;
                    uint32_t hp = pack_hi(v[e], v[e+1], lo0, lo1);
                    uint32_t lp = pack_bf(lo0, lo1);
                    int off = (((2*i + p) & 3) * 16) + ((i >> 1) * 8);
                    *reinterpret_cast<uint32_t*>(ah + off) = hp;
                    *reinterpret_cast<uint32_t*>(al + off) = lp;
                }
        }
        // B copy (fragment layout already)
        const unsigned long long* wh = g_Whi + c * 1280;
        const unsigned long long* wl = g_Wlo + c * 1280;
        unsigned long long* bh = reinterpret_cast<unsigned long long*>(sm + buf * BUFSZ + B_HI);
        unsigned long long* bl = reinterpret_cast<unsigned long long*>(sm + buf * BUFSZ + B_LO);
        const int nb = ksn * 640;
        for (int i = t; i < nb; i += 256) { bh[i] = wh[i]; bl[i] = wl[i]; }
    };

    stage(0, 0);
    __syncthreads();

    for (int c = 0; c < 25; c++) {
        if (c + 1 < 25) stage((c + 1) & 1, c + 1);
        // compute chunk c
        const char* sb = sm + (c & 1) * BUFSZ;
        const int ksn = (c == 24) ? 1 : 2;
#pragma unroll 1
        for (int ks = 0; ks < ksn; ks++) {
            uint4 ah = *reinterpret_cast<const uint4*>(
                sb + A_HI + ((ks * 8 + wid) * 32 + lane) * 16);
            uint4 al = *reinterpret_cast<const uint4*>(
                sb + A_LO + ((ks * 8 + wid) * 32 + lane) * 16);
            const unsigned long long* bh =
                reinterpret_cast<const unsigned long long*>(sb + B_HI) + ks * 640 + lane;
            const unsigned long long* bl =
                reinterpret_cast<const unsigned long long*>(sb + B_LO) + ks * 640 + lane;
#pragma unroll
            for (int nt = 0; nt < 20; nt++) {
                unsigned long long h = bh[nt * 32], l = bl[nt * 32];
                uint32_t h0 = (uint32_t)h, h1 = (uint32_t)(h >> 32);
                uint32_t l0 = (uint32_t)l, l1 = (uint32_t)(l >> 32);
                MMA_BF16(acc[nt], ah, h0, h1);
                MMA_BF16(acc[nt], ah, l0, l1);
                MMA_BF16(acc[nt], al, h0, h1);
            }
        }
        __syncthreads();
    }

    // epilogue: D frag (g, 2tg) rows wid*16+g / +8
    const int r0 = m0 + wid * 16 + g;
    const int col0 = tg * 2;
#pragma unroll
    for (int nt = 0; nt < 20; nt++) {
        float2 a = make_float2(acc[nt][0], acc[nt][1]);
        float2 b = make_float2(acc[nt][2], acc[nt][3]);
        *reinterpret_cast<float2*>(g_u + (long long)r0 * NTOT + nt * 8 + col0) = a;
        *reinterpret_cast<float2*>(g_u + (long long)(r0 + 8) * NTOT + nt * 8 + col0) = b;
    }
}

// ---------------------------------------------------------------------------
// Kernel 2: EI recurrence. 128 CTAs x 384 thr, 4 batch rows per CTA.
// Threads 0..319: neuron o = (t>>5)*16 + ((t&31)>>1), K-half kh = t&1,
//   80 folded weights in registers, shfl-xor(1) reduce, 1 barrier/step.
// Threads 320..383: readout warps, run one step behind (fully overlapped).
// ---------------------------------------------------------------------------
__global__ __launch_bounds__(384) void rec_kernel(
    const float* __restrict__ Wee, const float* __restrict__ Wie,
    const float* __restrict__ Wei, const float* __restrict__ Wii,
    const float* __restrict__ be,  const float* __restrict__ bi,
    const float* __restrict__ Wro, const float* __restrict__ bro,
    float* __restrict__ out)
{
    __shared__ __align__(16) float Wro_s[10 * 128];
    __shared__ __align__(16) float rc[2][4][160];

    const int t  = threadIdx.x;
    const int b0 = blockIdx.x * 4;

    for (int i = t; i < 10 * 128; i += 384) Wro_s[i] = Wro[i];
    for (int i = t; i < 2 * 4 * 160; i += 384) (&rc[0][0][0])[i] = 0.f;

    float* out_logits = out;
    float* out_last   = out_logits + (long long)NB * NL * NC;
    float* out_re     = out_last   + (long long)NB * NC;
    float* out_ri     = out_re     + (long long)NB * NL * NE;
    float* out_bale   = out_ri     + (long long)NB * NL * NI;
    float* out_bali   = out_bale   + (long long)NB * NL * NE;

    if (t < 320) {
        const int o  = ((t >> 5) * 16) + ((t & 31) >> 1);
        const int kh = t & 1;
        const bool even = (kh == 0);

        // fold weights into registers: k<128 -> relu(E), k>=128 -> -relu(I)
        float w[80];
        const float* E; const float* I;
        if (o < NE) { E = Wee + (long long)o * NE; I = Wie + (long long)o * NI; }
        else        { E = Wei + (long long)(o - NE) * NE; I = Wii + (long long)(o - NE) * NI; }
#pragma unroll
        for (int q = 0; q < 20; q++) {
            int k = kh * 80 + q * 4;
            float4 f;
            if (k < NE) {
                f = *reinterpret_cast<const float4*>(E + k);
                w[q*4+0] = fmaxf(f.x, 0.f); w[q*4+1] = fmaxf(f.y, 0.f);
                w[q*4+2] = fmaxf(f.z, 0.f); w[q*4+3] = fmaxf(f.w, 0.f);
            } else {
                f = *reinterpret_cast<const float4*>(I + (k - NE));
                w[q*4+0] = -fmaxf(f.x, 0.f); w[q*4+1] = -fmaxf(f.y, 0.f);
                w[q*4+2] = -fmaxf(f.z, 0.f); w[q*4+3] = -fmaxf(f.w, 0.f);
            }
        }
        const float bias = (o < NE) ? be[o] : bi[o - NE];
        float st0 = 0.f, st1 = 0.f, st2 = 0.f, st3 = 0.f;

        __syncthreads();   // pre-loop barrier (matches RO branch)

        const float* up = g_u + (long long)b0 * NL * NTOT + o;
        float u0 = 0.f, u1 = 0.f, u2 = 0.f, u3 = 0.f;
        if (even) {
            u0 = up[0 * NL * NTOT]; u1 = up[1 * NL * NTOT];
            u2 = up[2 * NL * NTOT]; u3 = up[3 * NL * NTOT];
        }

        int cur = 0;
        for (int stp = 0; stp < NL; stp++) {
            float a0 = u0, a1 = u1, a2 = u2, a3 = u3;
            // prefetch next step's u
            if (even && stp + 1 < NL) {
                int off = (stp + 1) * NTOT;
                u0 = up[0 * NL * NTOT + off]; u1 = up[1 * NL * NTOT + off];
                u2 = up[2 * NL * NTOT + off]; u3 = up[3 * NL * NTOT + off];
            }
            const float* rb = &rc[cur][0][kh * 80];
#pragma unroll
            for (int q = 0; q < 20; q++) {
                float4 x0 = *reinterpret_cast<const float4*>(rb + q * 4);
                float4 x1 = *reinterpret_cast<const float4*>(rb + 160 + q * 4);
                float4 x2 = *reinterpret_cast<const float4*>(rb + 320 + q * 4);
                float4 x3 = *reinterpret_cast<const float4*>(rb + 480 + q * 4);
                float w0 = w[q*4+0], w1 = w[q*4+1], w2 = w[q*4+2], w3 = w[q*4+3];
                a0 = fmaf(w0, x0.x, a0); a0 = fmaf(w1, x0.y, a0);
                a0 = fmaf(w2, x0.z, a0); a0 = fmaf(w3, x0.w, a0);
                a1 = fmaf(w0, x1.x, a1); a1 = fmaf(w1, x1.y, a1);
                a1 = fmaf(w2, x1.z, a1); a1 = fmaf(w3, x1.w, a1);
                a2 = fmaf(w0, x2.x, a2); a2 = fmaf(w1, x2.y, a2);
                a2 = fmaf(w2, x2.z, a2); a2 = fmaf(w3, x2.w, a2);
                a3 = fmaf(w0, x3.x, a3); a3 = fmaf(w1, x3.y, a3);
                a3 = fmaf(w2, x3.z, a3); a3 = fmaf(w3, x3.w, a3);
            }
            a0 += __shfl_xor_sync(0xFFFFFFFFu, a0, 1);
            a1 += __shfl_xor_sync(0xFFFFFFFFu, a1, 1);
            a2 += __shfl_xor_sync(0xFFFFFFFFu, a2, 1);
            a3 += __shfl_xor_sync(0xFFFFFFFFu, a3, 1);

            st0 = 0.5f * st0 + 0.5f * (a0 + bias);
            st1 = 0.5f * st1 + 0.5f * (a1 + bias);
            st2 = 0.5f * st2 + 0.5f * (a2 + bias);
            st3 = 0.5f * st3 + 0.5f * (a3 + bias);
            float r0 = fmaxf(st0, 0.f), r1 = fmaxf(st1, 0.f);
            float r2 = fmaxf(st2, 0.f), r3 = fmaxf(st3, 0.f);

            if (even) {
                float bal[4] = {a0, a1, a2, a3};
                float rv[4]  = {r0, r1, r2, r3};
#pragma unroll
                for (int r = 0; r < 4; r++) {
                    long long row = (long long)(b0 + r) * NL + stp;
                    if (o < NE) {
                        out_bale[row * NE + o] = bal[r];
                        out_re[row * NE + o]   = rv[r];
                    } else {
                        out_bali[row * NI + (o - NE)] = bal[r];
                        out_ri[row * NI + (o - NE)]   = rv[r];
                    }
                    rc[cur ^ 1][r][o] = rv[r];
                }
            }
            __syncthreads();
            cur ^= 1;
        }
    } else {
        // readout warps: logits for step stp computed right after its barrier
        const int rid = t - 320;
        const bool act = (rid < 40);
        const int r = rid / 10, c = rid % 10;
        const float bro_c = act ? bro[c] : 0.f;

        __syncthreads();   // pre-loop barrier
        int cur = 0;
        for (int stp = 0; stp < NL; stp++) {
            __syncthreads();   // state for step stp now published in rc[cur^1]
            if (act) {
                float acc = bro_c;
                const float4* wr = reinterpret_cast<const float4*>(Wro_s + c * 128);
                const float4* xr = reinterpret_cast<const float4*>(&rc[cur ^ 1][r][0]);
#pragma unroll
                for (int q = 0; q < 32; q++) {
                    float4 wq = wr[q], xq = xr[q];
                    acc = fmaf(wq.x, xq.x, acc); acc = fmaf(wq.y, xq.y, acc);
                    acc = fmaf(wq.z, xq.z, acc); acc = fmaf(wq.w, xq.w, acc);
                }
                long long row = (long long)(b0 + r) * NL + stp;
                out_logits[row * NC + c] = acc;
                if (stp == NL - 1) out_last[(long long)(b0 + r) * NC + c] = acc;
            }
            cur ^= 1;
        }
    }
}

// ---------------------------------------------------------------------------
extern "C" void kernel_launch(void* const* d_in, const int* in_sizes, int n_in,
                              void* d_out, int out_size) {
    const float* x   = (const float*)d_in[0];
    const float* Wxe = (const float*)d_in[1];
    const float* Wxi = (const float*)d_in[2];
    const float* Wee = (const float*)d_in[3];
    const float* Wie = (const float*)d_in[4];
    const float* Wei = (const float*)d_in[5];
    const float* Wii = (const float*)d_in[6];
    const float* be  = (const float*)d_in[7];
    const float* bi  = (const float*)d_in[8];
    const float* Wro = (const float*)d_in[9];
    const float* bro = (const float*)d_in[10];
    float* out = (float*)d_out;

    cudaFuncSetAttribute(proj_kernel, cudaFuncAttributeMaxDynamicSharedMemorySize, PROJ_SMEM);

    wconv_kernel<<<(NKS * NNT * 32 + 255) / 256, 256>>>(Wxe, Wxi);
    proj_kernel<<<MT / 128, 256, PROJ_SMEM>>>(x);
    rec_kernel<<<NB / 4, 384>>>(Wee, Wie, Wei, Wii, be, bi, Wro, bro, out);
}